// round 8
// baseline (speedup 1.0000x reference)
#include <cuda_runtime.h>

#define ESP 1e-12f
#define C_DIM 8192
#define THREADS 256

__device__ double        g_accum;   // zero-init; reset by finalizer each run
__device__ unsigned int  g_ticket;  // zero-init; reset by finalizer each run

__device__ __forceinline__ float fsqrt_approx(float x) {
    float r;
    asm("sqrt.approx.f32 %0, %1;" : "=f"(r) : "f"(x));
    return r;
}

// 256-bit global load (sm_100+): SASS LDG.E.256, one instruction per 32 bytes.
__device__ __forceinline__ void ldg256(const float* __restrict__ a, float v[8]) {
    asm("ld.global.nc.v8.f32 {%0,%1,%2,%3,%4,%5,%6,%7}, [%8];"
        : "=f"(v[0]), "=f"(v[1]), "=f"(v[2]), "=f"(v[3]),
          "=f"(v[4]), "=f"(v[5]), "=f"(v[6]), "=f"(v[7])
        : "l"(a));
}

// Pin 8 blocks/SM (regs <= 32): Round-6 showed +3 regs drops residency to
// 7/SM and costs ~6% DRAM utilization.
__global__ void __launch_bounds__(THREADS, 8) mfl_fused_kernel(
    const float* __restrict__ p,
    const float* __restrict__ g,
    float* __restrict__ out,
    int n_rows)
{
    const int row = blockIdx.x;
    const float* __restrict__ pr = p + (size_t)row * C_DIM;
    const float* __restrict__ gr = g + (size_t)row * C_DIM;
    const int tid = threadIdx.x;

    float sum = 0.0f;
    int   cnt = 0;

    // C_DIM/8 = 1024 v8-chunks, 256 threads -> 4 iterations of one
    // 256-bit load pair (p, g) each.
    #pragma unroll
    for (int i = 0; i < 4; i++) {
        const int base = (tid + i * THREADS) * 8;
        float pv[8], gv[8];
        ldg256(pr + base, pv);
        ldg256(gr + base, gv);

        #pragma unroll
        for (int k = 0; k < 8; k++) {
            float pe = pv[k];
            float ge = gv[k];
            float a = fmaf(pe, ge, ESP);
            float b = fmaf(1.0f - pe, 1.0f - ge, ESP);
            float l = 1.0f - (fsqrt_approx(a) + fsqrt_approx(b));
            bool nz = (ge != 0.0f);
            sum += nz ? l : 0.0f;
            cnt += nz ? 1 : 0;
        }
    }

    // Warp reduction
    #pragma unroll
    for (int o = 16; o > 0; o >>= 1) {
        sum += __shfl_down_sync(0xffffffffu, sum, o);
        cnt += __shfl_down_sync(0xffffffffu, cnt, o);
    }

    __shared__ float s_sum[THREADS / 32];
    __shared__ int   s_cnt[THREADS / 32];
    const int wid = tid >> 5;
    const int lid = tid & 31;
    if (lid == 0) {
        s_sum[wid] = sum;
        s_cnt[wid] = cnt;
    }
    __syncthreads();

    if (tid == 0) {
        float bsum = 0.0f;
        int   bcnt = 0;
        #pragma unroll
        for (int w = 0; w < THREADS / 32; w++) {
            bsum += s_sum[w];
            bcnt += s_cnt[w];
        }
        float row_loss = (bcnt > 0) ? (bsum / (float)bcnt) : 0.0f;

        atomicAdd(&g_accum, (double)row_loss);
        __threadfence();
        unsigned int t = atomicAdd(&g_ticket, 1u);
        if (t == (unsigned int)(gridDim.x - 1)) {
            // Last block: read-and-reset accumulator + ticket atomically so
            // every graph replay starts from zeroed state (matches the
            // zero-initialized first call), then emit the result.
            unsigned long long bits =
                atomicExch((unsigned long long*)&g_accum, 0ull);
            atomicExch(&g_ticket, 0u);
            double total = __longlong_as_double((long long)bits);
            out[0] = (float)(total / (double)n_rows);
        }
    }
}

extern "C" void kernel_launch(void* const* d_in, const int* in_sizes, int n_in,
                              void* d_out, int out_size) {
    const float* p = (const float*)d_in[0];
    const float* g = (const float*)d_in[1];
    float* out = (float*)d_out;

    const int total = in_sizes[0];
    const int n_rows = total / C_DIM;   // 16384

    mfl_fused_kernel<<<n_rows, THREADS>>>(p, g, out, n_rows);
}

// round 9
// speedup vs baseline: 1.0047x; 1.0047x over previous
#include <cuda_runtime.h>

#define ESP 1e-12f
#define C_DIM 8192
#define THREADS 256

__device__ double        g_accum;   // zero-init; reset by finalizer each run
__device__ unsigned int  g_ticket;  // zero-init; reset by finalizer each run

__device__ __forceinline__ float fsqrt_approx(float x) {
    float r;
    asm("sqrt.approx.f32 %0, %1;" : "=f"(r) : "f"(x));
    return r;
}

// Pin 8 blocks/SM (regs <= 32): Round-6 showed that +3 regs drops residency
// to 7/SM and costs ~6% DRAM utilization. This bound locks in the layout.
__global__ void __launch_bounds__(THREADS, 8) mfl_fused_kernel(
    const float* __restrict__ p,
    const float* __restrict__ g,
    float* __restrict__ out,
    int n_rows)
{
    const int row = blockIdx.x;
    const float4* __restrict__ p4 =
        reinterpret_cast<const float4*>(p + (size_t)row * C_DIM);
    const float4* __restrict__ g4 =
        reinterpret_cast<const float4*>(g + (size_t)row * C_DIM);
    const int tid = threadIdx.x;

    float sum = 0.0f;
    int   cnt = 0;

    // C_DIM/4 = 2048 float4s, 256 threads -> 8 iterations. Streaming loads:
    // data is touched exactly once, keep it evict-first in L2.
    #pragma unroll
    for (int i = 0; i < 8; i++) {
        float4 pv = __ldcs(&p4[tid + i * THREADS]);
        float4 gv = __ldcs(&g4[tid + i * THREADS]);

        #pragma unroll
        for (int k = 0; k < 4; k++) {
            float pe = (&pv.x)[k];
            float ge = (&gv.x)[k];
            float a = fmaf(pe, ge, ESP);
            float b = fmaf(1.0f - pe, 1.0f - ge, ESP);
            float l = 1.0f - (fsqrt_approx(a) + fsqrt_approx(b));
            bool nz = (ge != 0.0f);
            sum += nz ? l : 0.0f;
            cnt += nz ? 1 : 0;
        }
    }

    // Warp reduction
    #pragma unroll
    for (int o = 16; o > 0; o >>= 1) {
        sum += __shfl_down_sync(0xffffffffu, sum, o);
        cnt += __shfl_down_sync(0xffffffffu, cnt, o);
    }

    __shared__ float s_sum[THREADS / 32];
    __shared__ int   s_cnt[THREADS / 32];
    const int wid = tid >> 5;
    const int lid = tid & 31;
    if (lid == 0) {
        s_sum[wid] = sum;
        s_cnt[wid] = cnt;
    }
    __syncthreads();

    if (tid == 0) {
        float bsum = 0.0f;
        int   bcnt = 0;
        #pragma unroll
        for (int w = 0; w < THREADS / 32; w++) {
            bsum += s_sum[w];
            bcnt += s_cnt[w];
        }
        float row_loss = (bcnt > 0) ? (bsum / (float)bcnt) : 0.0f;

        atomicAdd(&g_accum, (double)row_loss);
        __threadfence();
        unsigned int t = atomicAdd(&g_ticket, 1u);
        if (t == (unsigned int)(gridDim.x - 1)) {
            // Last block: read-and-reset accumulator + ticket atomically so
            // every graph replay starts from zeroed state (matches the
            // zero-initialized first call), then emit the result.
            unsigned long long bits =
                atomicExch((unsigned long long*)&g_accum, 0ull);
            atomicExch(&g_ticket, 0u);
            double total = __longlong_as_double((long long)bits);
            out[0] = (float)(total / (double)n_rows);
        }
    }
}

extern "C" void kernel_launch(void* const* d_in, const int* in_sizes, int n_in,
                              void* d_out, int out_size) {
    const float* p = (const float*)d_in[0];
    const float* g = (const float*)d_in[1];
    float* out = (float*)d_out;

    const int total = in_sizes[0];
    const int n_rows = total / C_DIM;   // 16384

    mfl_fused_kernel<<<n_rows, THREADS>>>(p, g, out, n_rows);
}